// round 1
// baseline (speedup 1.0000x reference)
#include <cuda_runtime.h>
#include <math.h>

// Problem constants (fixed by the dataset)
constexpr int Bc   = 2;
constexpr int Nn   = 5456;
constexpr int Sc   = 5456;   // total flattened map size == N here
constexpr int Hc   = 8;
constexpr int Lc   = 5;
constexpr int Pc   = 4;
constexpr int Dh   = 32;     // head dim
constexpr int Kin  = 256;    // IN_SIZE == SAMPLE_SIZE
constexpr int Mtot = Bc * Nn;          // 10912
constexpr int NPT  = Lc * Pc;          // 20 points per head
constexpr int OFFC = Hc * NPT * 3;     // 480
constexpr int ATTC = Hc * NPT;         // 160

// Scratch (static device globals — allocation-free)
__device__ float g_val[(size_t)Bc * Hc * Sc * Dh];   // [B,H,S,32]
__device__ float g_off[(size_t)Mtot * OFFC];         // [M,480]
__device__ float g_logit[(size_t)Mtot * ATTC];       // [M,160]
__device__ float g_weighted[(size_t)Mtot * 256];     // [M,256]

// ---------------------------------------------------------------------------
// Generic fp32 GEMM: C[m,o] = sum_k A[m,k] * W[o,k] + bias[o]
// MODE 1: epilogue scatters into g_val with [B,H,S,32] layout
// MODE 2: writes g_off   MODE 3: writes g_logit
// MODE 4: A source is g_weighted, writes Cout (final output)
// MODE 0: plain Cout
// Tile: BM=BN=64, BK=16, 256 threads, 4x4 per thread.
// ---------------------------------------------------------------------------
template <int MODE>
__global__ __launch_bounds__(256) void gemm_nt(
    const float* __restrict__ A, const float* __restrict__ W,
    const float* __restrict__ bias, float* __restrict__ Cout,
    int M, int O)
{
    __shared__ float As[16][68];   // [k][m], padded: row stride 272B (16B aligned)
    __shared__ float Bs[16][68];   // [k][o]

    const int tid = threadIdx.x;
    const int tx = tid & 15;
    const int ty = tid >> 4;
    const int row0 = blockIdx.y * 64;
    const int col0 = blockIdx.x * 64;

    const float* __restrict__ Ap = (MODE == 4) ? g_weighted : A;

    float acc[4][4] = {};

    for (int kt = 0; kt < Kin; kt += 16) {
#pragma unroll
        for (int i = 0; i < 4; i++) {
            int e = tid + i * 256;       // 0..1023
            int r = e >> 4;              // tile row 0..63
            int c = e & 15;              // tile k   0..15
            int gm = row0 + r;
            As[c][r] = (gm < M) ? Ap[(size_t)gm * Kin + kt + c] : 0.f;
            int go = col0 + r;
            Bs[c][r] = (go < O) ? W[(size_t)go * Kin + kt + c] : 0.f;
        }
        __syncthreads();
#pragma unroll
        for (int k = 0; k < 16; k++) {
            float4 a4 = *(const float4*)&As[k][ty * 4];
            float4 b4 = *(const float4*)&Bs[k][tx * 4];
            float av[4] = {a4.x, a4.y, a4.z, a4.w};
            float bv[4] = {b4.x, b4.y, b4.z, b4.w};
#pragma unroll
            for (int i = 0; i < 4; i++)
#pragma unroll
                for (int j = 0; j < 4; j++)
                    acc[i][j] += av[i] * bv[j];
        }
        __syncthreads();
    }

#pragma unroll
    for (int i = 0; i < 4; i++) {
        int m = row0 + ty * 4 + i;
        if (m >= M) continue;
#pragma unroll
        for (int j = 0; j < 4; j++) {
            int o = col0 + tx * 4 + j;
            if (o >= O) continue;
            float v = acc[i][j] + bias[o];
            if (MODE == 1) {
                int b = m / Sc, s = m % Sc;
                int h = o >> 5, d = o & 31;
                g_val[(((size_t)(b * Hc + h)) * Sc + s) * Dh + d] = v;
            } else if (MODE == 2) {
                g_off[(size_t)m * OFFC + o] = v;
            } else if (MODE == 3) {
                g_logit[(size_t)m * ATTC + o] = v;
            } else {
                Cout[(size_t)m * O + o] = v;
            }
        }
    }
}

// ---------------------------------------------------------------------------
// Fused: loc computation + softmax + trilinear sample + attention weighting.
// One block per token m = b*N + n. 256 threads = 8 warps; warp = head,
// lane = head-dim channel. All corner/branch logic is warp-uniform.
// Writes g_weighted[m, h*32+d].
// ---------------------------------------------------------------------------
__global__ __launch_bounds__(256) void sample_kernel(
    const float* __restrict__ priors,       // [B,N,L,2]
    const int* __restrict__ map_shapes,     // [L,2] rows (dim0,dim1); W=shapes[l][1], H=shapes[l][0]
    const int* __restrict__ start_ids)      // [L]
{
    const int m = blockIdx.x;               // b*N + n
    const int b = m / Nn;

    __shared__ float s_off[OFFC];
    __shared__ float s_logit[ATTC];
    __shared__ float s_attn[ATTC];
    __shared__ float s_loc[ATTC][3];
    __shared__ float s_wh[Lc][2];
    __shared__ int   s_start[Lc];

    const int tid = threadIdx.x;
    if (tid < Lc) {
        s_wh[tid][0] = (float)map_shapes[tid * 2 + 1];  // W
        s_wh[tid][1] = (float)map_shapes[tid * 2 + 0];  // H
        s_start[tid] = start_ids[tid];
    }
    for (int i = tid; i < OFFC; i += 256) s_off[i]   = g_off[(size_t)m * OFFC + i];
    for (int i = tid; i < ATTC; i += 256) s_logit[i] = g_logit[(size_t)m * ATTC + i];
    __syncthreads();

    if (tid < ATTC) {
        int h  = tid / NPT;
        int lp = tid % NPT;
        int l  = lp / Pc;
        float Wf = s_wh[l][0], Hf = s_wh[l][1];
        float px = priors[((size_t)m * Lc + l) * 2 + 0];
        float py = priors[((size_t)m * Lc + l) * 2 + 1];
        s_loc[tid][0] = px + s_off[tid * 3 + 0] / Wf;
        s_loc[tid][1] = py + s_off[tid * 3 + 1] / Hf;
        s_loc[tid][2] = (float)l * (1.0f / (Lc - 1)) + s_off[tid * 3 + 2];
        // softmax over the 20 points of this head
        float mx = -1e30f;
        for (int j = 0; j < NPT; j++) mx = fmaxf(mx, s_logit[h * NPT + j]);
        float sum = 0.f;
        for (int j = 0; j < NPT; j++) sum += __expf(s_logit[h * NPT + j] - mx);
        s_attn[tid] = __expf(s_logit[tid] - mx) / sum;
    }
    __syncthreads();

    const int warp = tid >> 5;
    const int lane = tid & 31;
    const int h = warp;
    const float* __restrict__ vb = g_val + ((size_t)(b * Hc + h)) * Sc * Dh;

    float acc = 0.f;
    for (int lp = 0; lp < NPT; lp++) {
        int t = h * NPT + lp;
        float lx = s_loc[t][0];
        float ly = s_loc[t][1];
        float lz = s_loc[t][2];
        float a  = s_attn[t];

        float z = fminf(fmaxf(lz, 0.f), 1.f) * (float)(Lc - 1);
        int z0 = min((int)z, Lc - 2);           // z >= 0, floor via trunc
        float wz = z - (float)z0;

        float res = 0.f;
#pragma unroll
        for (int q = 0; q < 2; q++) {
            int lvl = z0 + q;
            float wl = q ? wz : (1.f - wz);
            float Wf = s_wh[lvl][0], Hf = s_wh[lvl][1];
            int Wi = (int)Wf, Hi = (int)Hf;
            int offb = s_start[lvl];
            float x = lx * Wf - 0.5f;
            float y = ly * Hf - 0.5f;
            float x0f = floorf(x), y0f = floorf(y);
            float dx = x - x0f, dy = y - y0f;
            int x0 = (int)x0f, y0 = (int)y0f;

            float w00 = (1.f - dx) * (1.f - dy);
            float w10 = dx * (1.f - dy);
            float w01 = (1.f - dx) * dy;
            float w11 = dx * dy;

            float s = 0.f;
            // corner (x0, y0)
            if (x0 >= 0 && x0 < Wi && y0 >= 0 && y0 < Hi)
                s += w00 * vb[((size_t)(offb + y0 * Wi + x0)) * Dh + lane];
            // corner (x0+1, y0)
            if (x0 + 1 >= 0 && x0 + 1 < Wi && y0 >= 0 && y0 < Hi)
                s += w10 * vb[((size_t)(offb + y0 * Wi + x0 + 1)) * Dh + lane];
            // corner (x0, y0+1)
            if (x0 >= 0 && x0 < Wi && y0 + 1 >= 0 && y0 + 1 < Hi)
                s += w01 * vb[((size_t)(offb + (y0 + 1) * Wi + x0)) * Dh + lane];
            // corner (x0+1, y0+1)
            if (x0 + 1 >= 0 && x0 + 1 < Wi && y0 + 1 >= 0 && y0 + 1 < Hi)
                s += w11 * vb[((size_t)(offb + (y0 + 1) * Wi + x0 + 1)) * Dh + lane];

            res += wl * s;
        }
        acc += a * res;
    }
    g_weighted[(size_t)m * 256 + h * Dh + lane] = acc;
}

// ---------------------------------------------------------------------------
// kernel_launch
// Inputs (metadata order):
//  0 in_feats [B,N,256] f32     1 sample_priors [B,N,L,2] f32
//  2 sample_feats [B,N,256] f32 3 W_off [480,256]  4 b_off [480]
//  5 W_attn [160,256]           6 b_attn [160]
//  7 W_val [256,256]            8 b_val [256]
//  9 W_out [256,256]           10 b_out [256]
// 11 sample_map_shapes [L,2] i32   12 sample_map_start_ids [L] i32
// Output: [B,N,256] f32
// ---------------------------------------------------------------------------
extern "C" void kernel_launch(void* const* d_in, const int* in_sizes, int n_in,
                              void* d_out, int out_size)
{
    const float* in_feats  = (const float*)d_in[0];
    const float* priors    = (const float*)d_in[1];
    const float* sfeats    = (const float*)d_in[2];
    const float* W_off     = (const float*)d_in[3];
    const float* b_off     = (const float*)d_in[4];
    const float* W_attn    = (const float*)d_in[5];
    const float* b_attn    = (const float*)d_in[6];
    const float* W_val     = (const float*)d_in[7];
    const float* b_val     = (const float*)d_in[8];
    const float* W_out     = (const float*)d_in[9];
    const float* b_out     = (const float*)d_in[10];
    const int*   shapes    = (const int*)d_in[11];
    const int*   start_ids = (const int*)d_in[12];

    const int gridM = (Mtot + 63) / 64;   // 171

    // Value projection into [B,H,S,32] layout
    gemm_nt<1><<<dim3((256 + 63) / 64, gridM), 256>>>(sfeats, W_val, b_val, nullptr, Mtot, 256);
    // Offset projection
    gemm_nt<2><<<dim3((OFFC + 63) / 64, gridM), 256>>>(in_feats, W_off, b_off, nullptr, Mtot, OFFC);
    // Attention logits
    gemm_nt<3><<<dim3((ATTC + 63) / 64, gridM), 256>>>(in_feats, W_attn, b_attn, nullptr, Mtot, ATTC);
    // Fused loc + softmax + trilinear sample + attention weighting
    sample_kernel<<<Mtot, 256>>>(priors, shapes, start_ids);
    // Output projection
    gemm_nt<4><<<dim3((256 + 63) / 64, gridM), 256>>>(nullptr, W_out, b_out, (float*)d_out, Mtot, 256);
}

// round 2
// speedup vs baseline: 1.6423x; 1.6423x over previous
#include <cuda_runtime.h>
#include <math.h>

// Problem constants (fixed by the dataset)
constexpr int Bc   = 2;
constexpr int Nn   = 5456;
constexpr int Sc   = 5456;   // total flattened map size == N here
constexpr int Hc   = 8;
constexpr int Lc   = 5;
constexpr int Pc   = 4;
constexpr int Dh   = 32;     // head dim
constexpr int Kin  = 256;    // IN_SIZE == SAMPLE_SIZE
constexpr int Mtot = Bc * Nn;          // 10912
constexpr int NPT  = Lc * Pc;          // 20 points per head
constexpr int OFFC = Hc * NPT * 3;     // 480
constexpr int ATTC = Hc * NPT;         // 160

// Scratch (static device globals — allocation-free)
__device__ float g_val[(size_t)Bc * Hc * Sc * Dh];   // [B,H,S,32]
__device__ float g_off[(size_t)Mtot * OFFC];         // [M,480]
__device__ float g_logit[(size_t)Mtot * ATTC];       // [M,160]
__device__ float g_weighted[(size_t)Mtot * 256];     // [M,256]

// ---------------------------------------------------------------------------
// fp32 GEMM: C[m,o] = sum_k A[m,k] * W[o,k] + bias[o]
// BM=128, BN=64, BK=16, 256 threads, 8x4 accumulators per thread.
// MODE 1: epilogue scatters into g_val with [B,H,S,32] layout
// MODE 2: writes g_off   MODE 3: writes g_logit
// MODE 4: A source is g_weighted, writes Cout (final output)
// ---------------------------------------------------------------------------
template <int MODE>
__global__ __launch_bounds__(256) void gemm_nt(
    const float* __restrict__ A, const float* __restrict__ W,
    const float* __restrict__ bias, float* __restrict__ Cout,
    int M, int O)
{
    __shared__ float As[16][132];  // [k][m], padded
    __shared__ float Bs[16][68];   // [k][o], padded

    const int tid = threadIdx.x;
    const int tx = tid & 15;       // col group (4 cols each)
    const int ty = tid >> 4;       // row group (8 rows each)
    const int row0 = blockIdx.y * 128;
    const int col0 = blockIdx.x * 64;

    const float* __restrict__ Ap = (MODE == 4) ? g_weighted : A;

    float acc[8][4] = {};

    for (int kt = 0; kt < Kin; kt += 16) {
        // Load A tile: 128x16 = 2048 elems, 8 per thread
#pragma unroll
        for (int i = 0; i < 8; i++) {
            int e = tid + i * 256;
            int r = e >> 4;            // 0..127
            int c = e & 15;            // 0..15
            int gm = row0 + r;
            As[c][r] = (gm < M) ? Ap[(size_t)gm * Kin + kt + c] : 0.f;
        }
        // Load B tile: 64x16 = 1024 elems, 4 per thread
#pragma unroll
        for (int i = 0; i < 4; i++) {
            int e = tid + i * 256;
            int r = e >> 4;            // 0..63
            int c = e & 15;
            int go = col0 + r;
            Bs[c][r] = (go < O) ? W[(size_t)go * Kin + kt + c] : 0.f;
        }
        __syncthreads();
#pragma unroll
        for (int k = 0; k < 16; k++) {
            float4 a0 = *(const float4*)&As[k][ty * 8];
            float4 a1 = *(const float4*)&As[k][ty * 8 + 4];
            float4 b0 = *(const float4*)&Bs[k][tx * 4];
            float av[8] = {a0.x, a0.y, a0.z, a0.w, a1.x, a1.y, a1.z, a1.w};
            float bv[4] = {b0.x, b0.y, b0.z, b0.w};
#pragma unroll
            for (int i = 0; i < 8; i++)
#pragma unroll
                for (int j = 0; j < 4; j++)
                    acc[i][j] += av[i] * bv[j];
        }
        __syncthreads();
    }

#pragma unroll
    for (int i = 0; i < 8; i++) {
        int m = row0 + ty * 8 + i;
        if (m >= M) continue;
#pragma unroll
        for (int j = 0; j < 4; j++) {
            int o = col0 + tx * 4 + j;
            if (o >= O) continue;
            float v = acc[i][j] + bias[o];
            if (MODE == 1) {
                int b = m / Sc, s = m % Sc;
                int h = o >> 5, d = o & 31;
                g_val[(((size_t)(b * Hc + h)) * Sc + s) * Dh + d] = v;
            } else if (MODE == 2) {
                g_off[(size_t)m * OFFC + o] = v;
            } else if (MODE == 3) {
                g_logit[(size_t)m * ATTC + o] = v;
            } else {
                Cout[(size_t)m * O + o] = v;
            }
        }
    }
}

// ---------------------------------------------------------------------------
// Fused sampler, restructured:
//   Phase 1 (160 threads, one per (head,point)): compute loc + softmax, then
//     bake attention*level*bilinear*valid into 8 (index, weight) pairs in smem.
//   Phase 2: warp = head; lane = sub(0..3)*8 + ch(0..7). 4 points processed
//     in parallel per warp, each lane covers 4 channels via float4.
//     Main loop: LDS.64 (idx,w) + predicated LDG.128 + 4 FFMA. All 32-bit.
//   Reduce across the 4 sub-groups with shfl_xor, lanes 0..7 store float4.
// ---------------------------------------------------------------------------
__global__ __launch_bounds__(256) void sample_kernel(
    const float* __restrict__ priors,       // [B,N,L,2]
    const int* __restrict__ map_shapes,     // [L,2]; W=shapes[l][1], H=shapes[l][0]
    const int* __restrict__ start_ids)      // [L]
{
    const int m = blockIdx.x;               // b*N + n
    const int b = (m >= Nn) ? 1 : 0;

    __shared__ int2  s_tab[ATTC][8];        // {index, weight-as-int}
    __shared__ float s_logit[ATTC];
    __shared__ float s_wh[Lc][2];
    __shared__ int   s_start[Lc];

    const int tid = threadIdx.x;
    if (tid < Lc) {
        s_wh[tid][0] = (float)map_shapes[tid * 2 + 1];  // W
        s_wh[tid][1] = (float)map_shapes[tid * 2 + 0];  // H
        s_start[tid] = start_ids[tid];
    }
    for (int i = tid; i < ATTC; i += 256) s_logit[i] = g_logit[(size_t)m * ATTC + i];
    __syncthreads();

    if (tid < ATTC) {
        const int h  = tid / NPT;
        const int lp = tid % NPT;
        const int l  = lp / Pc;
        const float ox = g_off[(size_t)m * OFFC + tid * 3 + 0];
        const float oy = g_off[(size_t)m * OFFC + tid * 3 + 1];
        const float oz = g_off[(size_t)m * OFFC + tid * 3 + 2];
        const float Wl = s_wh[l][0], Hl = s_wh[l][1];
        const float px = priors[((size_t)m * Lc + l) * 2 + 0];
        const float py = priors[((size_t)m * Lc + l) * 2 + 1];
        const float lx = px + ox / Wl;
        const float ly = py + oy / Hl;
        const float lz = (float)l * (1.0f / (Lc - 1)) + oz;

        // softmax over this head's 20 points
        float mx = -1e30f;
        for (int j = 0; j < NPT; j++) mx = fmaxf(mx, s_logit[h * NPT + j]);
        float sum = 0.f;
        for (int j = 0; j < NPT; j++) sum += __expf(s_logit[h * NPT + j] - mx);
        const float a = __expf(s_logit[tid] - mx) / sum;

        // level interpolation
        float z = fminf(fmaxf(lz, 0.f), 1.f) * (float)(Lc - 1);
        int z0 = min((int)z, Lc - 2);
        float wz = z - (float)z0;

#pragma unroll
        for (int q = 0; q < 2; q++) {
            const int lvl = z0 + q;
            const float wl = a * (q ? wz : (1.f - wz));
            const float Wf = s_wh[lvl][0], Hf = s_wh[lvl][1];
            const int Wi = (int)Wf, Hi = (int)Hf;
            const int offb = s_start[lvl];
            const float x = lx * Wf - 0.5f;
            const float y = ly * Hf - 0.5f;
            const float x0f = floorf(x), y0f = floorf(y);
            const float dx = x - x0f, dy = y - y0f;
            const int x0 = (int)x0f, y0 = (int)y0f;

            const float cw[4] = {(1.f - dx) * (1.f - dy), dx * (1.f - dy),
                                 (1.f - dx) * dy,          dx * dy};
            const int cx[4] = {x0, x0 + 1, x0, x0 + 1};
            const int cy[4] = {y0, y0, y0 + 1, y0 + 1};
#pragma unroll
            for (int c = 0; c < 4; c++) {
                const bool valid = (cx[c] >= 0) & (cx[c] < Wi) & (cy[c] >= 0) & (cy[c] < Hi);
                const int idx = valid ? (offb + cy[c] * Wi + cx[c]) : 0;
                const float w = valid ? (wl * cw[c]) : 0.f;
                s_tab[tid][q * 4 + c] = make_int2(idx, __float_as_int(w));
            }
        }
    }
    __syncthreads();

    const int warp = tid >> 5;              // head
    const int lane = tid & 31;
    const int sub  = lane >> 3;             // which of 4 parallel points
    const int ch   = lane & 7;              // float4 channel group

    const float4* __restrict__ vb =
        (const float4*)g_val + (size_t)(b * Hc + warp) * Sc * 8;

    float4 acc = make_float4(0.f, 0.f, 0.f, 0.f);
#pragma unroll
    for (int g = 0; g < 5; g++) {
        const int t = warp * NPT + g * 4 + sub;
#pragma unroll
        for (int c = 0; c < 8; c++) {
            const int2 e = s_tab[t][c];
            const float w = __int_as_float(e.y);
            if (w != 0.f) {
                const float4 v = __ldg(&vb[e.x * 8 + ch]);
                acc.x += w * v.x;
                acc.y += w * v.y;
                acc.z += w * v.z;
                acc.w += w * v.w;
            }
        }
    }
    // reduce across the 4 sub-groups (lane xor 8, 16)
#pragma unroll
    for (int d = 8; d < 32; d <<= 1) {
        acc.x += __shfl_xor_sync(0xFFFFFFFFu, acc.x, d);
        acc.y += __shfl_xor_sync(0xFFFFFFFFu, acc.y, d);
        acc.z += __shfl_xor_sync(0xFFFFFFFFu, acc.z, d);
        acc.w += __shfl_xor_sync(0xFFFFFFFFu, acc.w, d);
    }
    if (lane < 8) {
        ((float4*)g_weighted)[(size_t)m * 64 + warp * 8 + ch] = acc;
    }
}

// ---------------------------------------------------------------------------
// kernel_launch — inputs in metadata order (see reference)
// ---------------------------------------------------------------------------
extern "C" void kernel_launch(void* const* d_in, const int* in_sizes, int n_in,
                              void* d_out, int out_size)
{
    const float* in_feats  = (const float*)d_in[0];
    const float* priors    = (const float*)d_in[1];
    const float* sfeats    = (const float*)d_in[2];
    const float* W_off     = (const float*)d_in[3];
    const float* b_off     = (const float*)d_in[4];
    const float* W_attn    = (const float*)d_in[5];
    const float* b_attn    = (const float*)d_in[6];
    const float* W_val     = (const float*)d_in[7];
    const float* b_val     = (const float*)d_in[8];
    const float* W_out     = (const float*)d_in[9];
    const float* b_out     = (const float*)d_in[10];
    const int*   shapes    = (const int*)d_in[11];
    const int*   start_ids = (const int*)d_in[12];

    const int gridM = (Mtot + 127) / 128;   // 86

    // Value projection into [B,H,S,32] layout
    gemm_nt<1><<<dim3((256 + 63) / 64, gridM), 256>>>(sfeats, W_val, b_val, nullptr, Mtot, 256);
    // Offset projection
    gemm_nt<2><<<dim3((OFFC + 63) / 64, gridM), 256>>>(in_feats, W_off, b_off, nullptr, Mtot, OFFC);
    // Attention logits
    gemm_nt<3><<<dim3((ATTC + 63) / 64, gridM), 256>>>(in_feats, W_attn, b_attn, nullptr, Mtot, ATTC);
    // Fused loc + softmax + trilinear sample + attention weighting
    sample_kernel<<<Mtot, 256>>>(priors, shapes, start_ids);
    // Output projection
    gemm_nt<4><<<dim3((256 + 63) / 64, gridM), 256>>>(nullptr, W_out, b_out, (float*)d_out, Mtot, 256);
}

// round 4
// speedup vs baseline: 2.1048x; 1.2816x over previous
#include <cuda_runtime.h>
#include <cuda_bf16.h>
#include <math.h>
#include <stdint.h>

// Problem constants
constexpr int Bc   = 2;
constexpr int Nn   = 5456;
constexpr int Sc   = 5456;
constexpr int Hc   = 8;
constexpr int Lc   = 5;
constexpr int Pc   = 4;
constexpr int Dh   = 32;
constexpr int Kin  = 256;
constexpr int KP   = 768;              // 3 * Kin
constexpr int Mtot = Bc * Nn;          // 10912
constexpr int NPT  = Lc * Pc;          // 20
constexpr int OFFC = Hc * NPT * 3;     // 480
constexpr int ATTC = Hc * NPT;         // 160

// Scratch (static device globals — allocation-free)
__device__ float g_val[(size_t)Bc * Hc * Sc * Dh];     // [B,H,S,32]
__device__ float g_off[(size_t)Mtot * OFFC];
__device__ float g_logit[(size_t)Mtot * ATTC];
__device__ __nv_bfloat16 gA_in[(size_t)Mtot * KP];     // A-side: (hi|lo|hi)
__device__ __nv_bfloat16 gA_sf[(size_t)Mtot * KP];
__device__ __nv_bfloat16 gA_w [(size_t)Mtot * KP];
__device__ __nv_bfloat16 gW_off [OFFC * KP];           // W-side: (hi|hi|lo)
__device__ __nv_bfloat16 gW_attn[ATTC * KP];
__device__ __nv_bfloat16 gW_val [256  * KP];
__device__ __nv_bfloat16 gW_out [256  * KP];

// ---------------------------------------------------------------------------
// PTX helpers
// ---------------------------------------------------------------------------
__device__ __forceinline__ void cp16(uint32_t dst, const void* src, int sz) {
    asm volatile("cp.async.cg.shared.global [%0], [%1], 16, %2;\n"
                 :: "r"(dst), "l"(src), "r"(sz));
}
__device__ __forceinline__ void cp_commit() {
    asm volatile("cp.async.commit_group;\n");
}
__device__ __forceinline__ void cp_wait1() {
    asm volatile("cp.async.wait_group 1;\n");
}
__device__ __forceinline__ void ldsm4(uint32_t* r, uint32_t a) {
    asm volatile("ldmatrix.sync.aligned.m8n8.x4.shared.b16 {%0,%1,%2,%3}, [%4];\n"
                 : "=r"(r[0]), "=r"(r[1]), "=r"(r[2]), "=r"(r[3]) : "r"(a));
}
__device__ __forceinline__ void mma16816(float* c, const uint32_t* a,
                                         uint32_t b0, uint32_t b1) {
    asm volatile(
        "mma.sync.aligned.m16n8k16.row.col.f32.bf16.bf16.f32 "
        "{%0,%1,%2,%3},{%4,%5,%6,%7},{%8,%9},{%0,%1,%2,%3};\n"
        : "+f"(c[0]), "+f"(c[1]), "+f"(c[2]), "+f"(c[3])
        : "r"(a[0]), "r"(a[1]), "r"(a[2]), "r"(a[3]), "r"(b0), "r"(b1));
}

// ---------------------------------------------------------------------------
// Decompose fp32 -> bf16 triples along K.
// A-side: (hi | lo | hi).  W-side: (hi | hi | lo).
// Dot product of the triples = Ahi·Whi + Alo·Whi + Ahi·Wlo  (3-term split).
// ---------------------------------------------------------------------------
__global__ __launch_bounds__(256) void decomp_a(
    const float* __restrict__ src, __nv_bfloat16* __restrict__ dst, int total)
{
    int i = blockIdx.x * 256 + threadIdx.x;
    if (i >= total) return;
    int m = i >> 8, k = i & 255;
    float x = src[i];
    __nv_bfloat16 hi = __float2bfloat16(x);
    __nv_bfloat16 lo = __float2bfloat16(x - __bfloat162float(hi));
    size_t b = (size_t)m * KP + k;
    dst[b]       = hi;
    dst[b + 256] = lo;
    dst[b + 512] = hi;
}

__global__ __launch_bounds__(256) void decomp_w(
    const float* __restrict__ src, __nv_bfloat16* __restrict__ dst, int total)
{
    int i = blockIdx.x * 256 + threadIdx.x;
    if (i >= total) return;
    int m = i >> 8, k = i & 255;
    float x = src[i];
    __nv_bfloat16 hi = __float2bfloat16(x);
    __nv_bfloat16 lo = __float2bfloat16(x - __bfloat162float(hi));
    size_t b = (size_t)m * KP + k;
    dst[b]       = hi;
    dst[b + 256] = hi;
    dst[b + 512] = lo;
}

// ---------------------------------------------------------------------------
// bf16 tensor-core GEMM: C[m,o] = sum_k A'[m,k] * W'[o,k] + bias[o]
// BM=128, BN=64, BK=32, K'=768, 256 threads, warp tile 32x32.
// Double-buffered cp.async. MODE 1: scatter g_val; 2: g_off; 3: g_logit;
// 4: plain Cout.
// ---------------------------------------------------------------------------
template <int MODE>
__global__ __launch_bounds__(256) void gemm_bf16(
    const __nv_bfloat16* __restrict__ A, const __nv_bfloat16* __restrict__ W,
    const float* __restrict__ bias, float* __restrict__ Cout,
    int M, int O)
{
    constexpr int AST = 40;   // bf16 row stride (32 + 8 pad) -> 80B
    __shared__ __nv_bfloat16 As[2][128 * AST];
    __shared__ __nv_bfloat16 Bs[2][64 * AST];

    const int tid  = threadIdx.x;
    const int warp = tid >> 5;
    const int lane = tid & 31;
    const int warpM = warp >> 1;      // 0..3
    const int warpN = warp & 1;       // 0..1
    const int row0 = blockIdx.y * 128;
    const int col0 = blockIdx.x * 64;

    const uint32_t sAs = (uint32_t)__cvta_generic_to_shared(&As[0][0]);
    const uint32_t sBs = (uint32_t)__cvta_generic_to_shared(&Bs[0][0]);
    constexpr uint32_t AS_STAGE = 128 * AST * 2;  // bytes
    constexpr uint32_t BS_STAGE = 64 * AST * 2;

    auto load_stage = [&](int kt, int s) {
        const int k0 = kt * 32;
#pragma unroll
        for (int p = 0; p < 2; p++) {
            int idx = tid + p * 256;
            int r = idx >> 2, c = idx & 3;
            int gm = row0 + r;
            const __nv_bfloat16* src = A + (size_t)(gm < M ? gm : M - 1) * KP + k0 + c * 8;
            uint32_t dst = sAs + s * AS_STAGE + (uint32_t)(r * AST + c * 8) * 2;
            cp16(dst, src, (gm < M) ? 16 : 0);
        }
        {
            int r = tid >> 2, c = tid & 3;
            int go = col0 + r;
            const __nv_bfloat16* src = W + (size_t)(go < O ? go : O - 1) * KP + k0 + c * 8;
            uint32_t dst = sBs + s * BS_STAGE + (uint32_t)(r * AST + c * 8) * 2;
            cp16(dst, src, (go < O) ? 16 : 0);
        }
    };

    float acc[2][4][4] = {};

    load_stage(0, 0);
    cp_commit();

    constexpr int NKT = KP / 32;   // 24
    for (int kt = 0; kt < NKT; kt++) {
        const int s = kt & 1;
        if (kt + 1 < NKT) load_stage(kt + 1, s ^ 1);
        cp_commit();
        cp_wait1();
        __syncthreads();

        const uint32_t aBase = sAs + s * AS_STAGE;
        const uint32_t bBase = sBs + s * BS_STAGE;
#pragma unroll
        for (int h = 0; h < 2; h++) {
            uint32_t afr[2][4], bfr[2][4];
#pragma unroll
            for (int mt = 0; mt < 2; mt++) {
                uint32_t addr = aBase +
                    (uint32_t)((warpM * 32 + mt * 16 + (lane & 15)) * AST +
                               h * 16 + (lane >> 4) * 8) * 2;
                ldsm4(afr[mt], addr);
            }
#pragma unroll
            for (int nt2 = 0; nt2 < 2; nt2++) {
                uint32_t addr = bBase +
                    (uint32_t)((warpN * 32 + nt2 * 16 + (lane & 15)) * AST +
                               h * 16 + (lane >> 4) * 8) * 2;
                ldsm4(bfr[nt2], addr);
            }
#pragma unroll
            for (int mt = 0; mt < 2; mt++)
#pragma unroll
                for (int nt = 0; nt < 4; nt++) {
                    uint32_t b0 = (nt & 1) ? bfr[nt >> 1][1] : bfr[nt >> 1][0];
                    uint32_t b1 = (nt & 1) ? bfr[nt >> 1][3] : bfr[nt >> 1][2];
                    mma16816(acc[mt][nt], afr[mt], b0, b1);
                }
        }
        __syncthreads();
    }

#pragma unroll
    for (int mt = 0; mt < 2; mt++) {
#pragma unroll
        for (int nt = 0; nt < 4; nt++) {
#pragma unroll
            for (int e = 0; e < 4; e++) {
                int m = row0 + warpM * 32 + mt * 16 + (lane >> 2) + (e >= 2 ? 8 : 0);
                int o = col0 + warpN * 32 + nt * 8 + 2 * (lane & 3) + (e & 1);
                if (m >= M || o >= O) continue;
                float v = acc[mt][nt][e] + bias[o];
                if (MODE == 1) {
                    int b = m / Sc, ss = m % Sc;
                    int hh = o >> 5, d = o & 31;
                    g_val[(((size_t)(b * Hc + hh)) * Sc + ss) * Dh + d] = v;
                } else if (MODE == 2) {
                    g_off[(size_t)m * OFFC + o] = v;
                } else if (MODE == 3) {
                    g_logit[(size_t)m * ATTC + o] = v;
                } else {
                    Cout[(size_t)m * O + o] = v;
                }
            }
        }
    }
}

// ---------------------------------------------------------------------------
// Fused sampler — writes decomposed (hi|lo|hi) bf16 A-operand directly.
// ---------------------------------------------------------------------------
__global__ __launch_bounds__(256) void sample_kernel(
    const float* __restrict__ priors,
    const int* __restrict__ map_shapes,
    const int* __restrict__ start_ids)
{
    const int m = blockIdx.x;
    const int b = (m >= Nn) ? 1 : 0;

    __shared__ int2  s_tab[ATTC][8];
    __shared__ float s_logit[ATTC];
    __shared__ float s_wh[Lc][2];
    __shared__ int   s_start[Lc];

    const int tid = threadIdx.x;
    if (tid < Lc) {
        s_wh[tid][0] = (float)map_shapes[tid * 2 + 1];  // W
        s_wh[tid][1] = (float)map_shapes[tid * 2 + 0];  // H
        s_start[tid] = start_ids[tid];
    }
    for (int i = tid; i < ATTC; i += 256) s_logit[i] = g_logit[(size_t)m * ATTC + i];
    __syncthreads();

    if (tid < ATTC) {
        const int h  = tid / NPT;
        const int lp = tid % NPT;
        const int l  = lp / Pc;
        const float ox = g_off[(size_t)m * OFFC + tid * 3 + 0];
        const float oy = g_off[(size_t)m * OFFC + tid * 3 + 1];
        const float oz = g_off[(size_t)m * OFFC + tid * 3 + 2];
        const float Wl = s_wh[l][0], Hl = s_wh[l][1];
        const float px = priors[((size_t)m * Lc + l) * 2 + 0];
        const float py = priors[((size_t)m * Lc + l) * 2 + 1];
        const float lx = px + ox / Wl;
        const float ly = py + oy / Hl;
        const float lz = (float)l * (1.0f / (Lc - 1)) + oz;

        float mx = -1e30f;
        for (int j = 0; j < NPT; j++) mx = fmaxf(mx, s_logit[h * NPT + j]);
        float sum = 0.f;
        for (int j = 0; j < NPT; j++) sum += __expf(s_logit[h * NPT + j] - mx);
        const float a = __expf(s_logit[tid] - mx) / sum;

        float z = fminf(fmaxf(lz, 0.f), 1.f) * (float)(Lc - 1);
        int z0 = min((int)z, Lc - 2);
        float wz = z - (float)z0;

#pragma unroll
        for (int q = 0; q < 2; q++) {
            const int lvl = z0 + q;
            const float wl = a * (q ? wz : (1.f - wz));
            const float Wf = s_wh[lvl][0], Hf = s_wh[lvl][1];
            const int Wi = (int)Wf, Hi = (int)Hf;
            const int offb = s_start[lvl];
            const float x = lx * Wf - 0.5f;
            const float y = ly * Hf - 0.5f;
            const float x0f = floorf(x), y0f = floorf(y);
            const float dx = x - x0f, dy = y - y0f;
            const int x0 = (int)x0f, y0 = (int)y0f;

            const float cw[4] = {(1.f - dx) * (1.f - dy), dx * (1.f - dy),
                                 (1.f - dx) * dy,          dx * dy};
            const int cx[4] = {x0, x0 + 1, x0, x0 + 1};
            const int cy[4] = {y0, y0, y0 + 1, y0 + 1};
#pragma unroll
            for (int c = 0; c < 4; c++) {
                const bool valid = (cx[c] >= 0) & (cx[c] < Wi) & (cy[c] >= 0) & (cy[c] < Hi);
                const int idx = valid ? (offb + cy[c] * Wi + cx[c]) : 0;
                const float w = valid ? (wl * cw[c]) : 0.f;
                s_tab[tid][q * 4 + c] = make_int2(idx, __float_as_int(w));
            }
        }
    }
    __syncthreads();

    const int warp = tid >> 5;
    const int lane = tid & 31;
    const int sub  = lane >> 3;
    const int ch   = lane & 7;

    const float4* __restrict__ vb =
        (const float4*)g_val + (size_t)(b * Hc + warp) * Sc * 8;

    float4 acc = make_float4(0.f, 0.f, 0.f, 0.f);
#pragma unroll
    for (int g = 0; g < 5; g++) {
        const int t = warp * NPT + g * 4 + sub;
#pragma unroll
        for (int c = 0; c < 8; c++) {
            const int2 e = s_tab[t][c];
            const float w = __int_as_float(e.y);
            if (w != 0.f) {
                const float4 v = __ldg(&vb[e.x * 8 + ch]);
                acc.x += w * v.x;
                acc.y += w * v.y;
                acc.z += w * v.z;
                acc.w += w * v.w;
            }
        }
    }
#pragma unroll
    for (int d = 8; d < 32; d <<= 1) {
        acc.x += __shfl_xor_sync(0xFFFFFFFFu, acc.x, d);
        acc.y += __shfl_xor_sync(0xFFFFFFFFu, acc.y, d);
        acc.z += __shfl_xor_sync(0xFFFFFFFFu, acc.z, d);
        acc.w += __shfl_xor_sync(0xFFFFFFFFu, acc.w, d);
    }
    if (lane < 8) {
        float v[4] = {acc.x, acc.y, acc.z, acc.w};
        size_t base = (size_t)m * KP + warp * 32 + ch * 4;
#pragma unroll
        for (int j = 0; j < 4; j++) {
            __nv_bfloat16 hi = __float2bfloat16(v[j]);
            __nv_bfloat16 lo = __float2bfloat16(v[j] - __bfloat162float(hi));
            gA_w[base + j]       = hi;
            gA_w[base + 256 + j] = lo;
            gA_w[base + 512 + j] = hi;
        }
    }
}

// ---------------------------------------------------------------------------
// kernel_launch
// ---------------------------------------------------------------------------
extern "C" void kernel_launch(void* const* d_in, const int* in_sizes, int n_in,
                              void* d_out, int out_size)
{
    const float* in_feats  = (const float*)d_in[0];
    const float* priors    = (const float*)d_in[1];
    const float* sfeats    = (const float*)d_in[2];
    const float* W_off     = (const float*)d_in[3];
    const float* b_off     = (const float*)d_in[4];
    const float* W_attn    = (const float*)d_in[5];
    const float* b_attn    = (const float*)d_in[6];
    const float* W_val     = (const float*)d_in[7];
    const float* b_val     = (const float*)d_in[8];
    const float* W_out     = (const float*)d_in[9];
    const float* b_out     = (const float*)d_in[10];
    const int*   shapes    = (const int*)d_in[11];
    const int*   start_ids = (const int*)d_in[12];

    __nv_bfloat16 *pA_in, *pA_sf, *pA_w, *pW_off, *pW_attn, *pW_val, *pW_out;
    cudaGetSymbolAddress((void**)&pA_in,  gA_in);
    cudaGetSymbolAddress((void**)&pA_sf,  gA_sf);
    cudaGetSymbolAddress((void**)&pA_w,   gA_w);
    cudaGetSymbolAddress((void**)&pW_off, gW_off);
    cudaGetSymbolAddress((void**)&pW_attn,gW_attn);
    cudaGetSymbolAddress((void**)&pW_val, gW_val);
    cudaGetSymbolAddress((void**)&pW_out, gW_out);

    // A-side decompositions: (hi | lo | hi)
    decomp_a<<<(Mtot * 256 + 255) / 256, 256>>>(in_feats, pA_in, Mtot * 256);
    decomp_a<<<(Mtot * 256 + 255) / 256, 256>>>(sfeats,  pA_sf, Mtot * 256);
    // W-side decompositions: (hi | hi | lo)
    decomp_w<<<(OFFC * 256 + 255) / 256, 256>>>(W_off,  pW_off,  OFFC * 256);
    decomp_w<<<(ATTC * 256 + 255) / 256, 256>>>(W_attn, pW_attn, ATTC * 256);
    decomp_w<<<(256  * 256 + 255) / 256, 256>>>(W_val,  pW_val,  256 * 256);
    decomp_w<<<(256  * 256 + 255) / 256, 256>>>(W_out,  pW_out,  256 * 256);

    const int gridM = (Mtot + 127) / 128;   // 86

    gemm_bf16<1><<<dim3(4, gridM), 256>>>(pA_sf, pW_val, b_val, nullptr, Mtot, 256);
    gemm_bf16<2><<<dim3(8, gridM), 256>>>(pA_in, pW_off, b_off, nullptr, Mtot, OFFC);
    gemm_bf16<3><<<dim3(3, gridM), 256>>>(pA_in, pW_attn, b_attn, nullptr, Mtot, ATTC);
    sample_kernel<<<Mtot, 256>>>(priors, shapes, start_ids);
    gemm_bf16<4><<<dim3(4, gridM), 256>>>(pA_w, pW_out, b_out, (float*)d_out, Mtot, 256);
}

// round 6
// speedup vs baseline: 2.4205x; 1.1500x over previous
#include <cuda_runtime.h>
#include <cuda_bf16.h>
#include <cuda_fp16.h>
#include <math.h>
#include <stdint.h>

// Problem constants
constexpr int Bc   = 2;
constexpr int Nn   = 5456;
constexpr int Sc   = 5456;
constexpr int Hc   = 8;
constexpr int Lc   = 5;
constexpr int Pc   = 4;
constexpr int Kin  = 256;
constexpr int KP   = 768;              // 3 * Kin
constexpr int Mtot = Bc * Nn;          // 10912
constexpr int NPT  = Lc * Pc;          // 20
constexpr int OFFC = Hc * NPT * 3;     // 480
constexpr int ATTC = Hc * NPT;         // 160
constexpr int OAC  = OFFC + ATTC;      // 640 (merged off+attn)

// Scratch (static device globals — allocation-free)
__device__ __half g_valh[(size_t)Bc * Hc * Sc * 32];   // [B,H,S,32] fp16
__device__ float g_off[(size_t)Mtot * OFFC];
__device__ float g_logit[(size_t)Mtot * ATTC];
__device__ __nv_bfloat16 gA_in[(size_t)Mtot * KP];     // A-side: (hi|lo|hi)
__device__ __nv_bfloat16 gA_sf[(size_t)Mtot * KP];
__device__ __nv_bfloat16 gA_w [(size_t)Mtot * KP];
__device__ __nv_bfloat16 gW_oa [OAC * KP];             // W-side: (hi|hi|lo), off|attn
__device__ __nv_bfloat16 gW_val[256 * KP];
__device__ __nv_bfloat16 gW_out[256 * KP];

// ---------------------------------------------------------------------------
// PTX helpers
// ---------------------------------------------------------------------------
__device__ __forceinline__ void cp16(uint32_t dst, const void* src, int sz) {
    asm volatile("cp.async.cg.shared.global [%0], [%1], 16, %2;\n"
                 :: "r"(dst), "l"(src), "r"(sz));
}
__device__ __forceinline__ void cp_commit() {
    asm volatile("cp.async.commit_group;\n");
}
__device__ __forceinline__ void cp_wait2() {
    asm volatile("cp.async.wait_group 2;\n");
}
__device__ __forceinline__ void ldsm4(uint32_t* r, uint32_t a) {
    asm volatile("ldmatrix.sync.aligned.m8n8.x4.shared.b16 {%0,%1,%2,%3}, [%4];\n"
                 : "=r"(r[0]), "=r"(r[1]), "=r"(r[2]), "=r"(r[3]) : "r"(a));
}
__device__ __forceinline__ void mma16816(float* c, const uint32_t* a,
                                         uint32_t b0, uint32_t b1) {
    asm volatile(
        "mma.sync.aligned.m16n8k16.row.col.f32.bf16.bf16.f32 "
        "{%0,%1,%2,%3},{%4,%5,%6,%7},{%8,%9},{%0,%1,%2,%3};\n"
        : "+f"(c[0]), "+f"(c[1]), "+f"(c[2]), "+f"(c[3])
        : "r"(a[0]), "r"(a[1]), "r"(a[2]), "r"(a[3]), "r"(b0), "r"(b1));
}

// ---------------------------------------------------------------------------
// A-side decompose: fp32 -> (hi | lo | hi) bf16 along K
// ---------------------------------------------------------------------------
__global__ __launch_bounds__(256) void decomp_a(
    const float* __restrict__ src, __nv_bfloat16* __restrict__ dst, int total)
{
    int i = blockIdx.x * 256 + threadIdx.x;
    if (i >= total) return;
    int m = i >> 8, k = i & 255;
    float x = src[i];
    __nv_bfloat16 hi = __float2bfloat16(x);
    __nv_bfloat16 lo = __float2bfloat16(x - __bfloat162float(hi));
    size_t b = (size_t)m * KP + k;
    dst[b]       = hi;
    dst[b + 256] = lo;
    dst[b + 512] = hi;
}

// ---------------------------------------------------------------------------
// All weight decomposes fused: (hi | hi | lo) into gW_oa / gW_val / gW_out
// ---------------------------------------------------------------------------
__global__ __launch_bounds__(256) void decomp_w_all(
    const float* __restrict__ Woff, const float* __restrict__ Wattn,
    const float* __restrict__ Wval, const float* __restrict__ Wout)
{
    int i = blockIdx.x * 256 + threadIdx.x;   // total rows: 640 + 256 + 256 = 1152
    int row = i >> 8, k = i & 255;
    float x;
    __nv_bfloat16* dst;
    int drow;
    if (row < OFFC)            { x = Woff [(size_t)row * 256 + k];          dst = gW_oa;  drow = row; }
    else if (row < OAC)        { x = Wattn[(size_t)(row - OFFC) * 256 + k]; dst = gW_oa;  drow = row; }
    else if (row < OAC + 256)  { x = Wval [(size_t)(row - OAC) * 256 + k];  dst = gW_val; drow = row - OAC; }
    else                       { x = Wout [(size_t)(row - OAC - 256) * 256 + k]; dst = gW_out; drow = row - OAC - 256; }
    __nv_bfloat16 hi = __float2bfloat16(x);
    __nv_bfloat16 lo = __float2bfloat16(x - __bfloat162float(hi));
    size_t b = (size_t)drow * KP + k;
    dst[b]       = hi;
    dst[b + 256] = hi;
    dst[b + 512] = lo;
}

// ---------------------------------------------------------------------------
// bf16 tensor-core GEMM: C[m,o] = sum_k A'[m,k] * W'[o,k] + bias[o]
// BM=128, BN=64, BK=32, 3-stage cp.async pipeline, 256 threads, warp 32x32.
// MODE 1: fp16 scatter into g_valh [B,H,S,32] (bias = b_val)
// MODE 2: merged off+attn: o<480 -> g_off (bias), o>=480 -> g_logit (bias2)
// MODE 4: plain fp32 Cout
// ---------------------------------------------------------------------------
template <int MODE>
__global__ __launch_bounds__(256) void gemm_bf16(
    const __nv_bfloat16* __restrict__ A, const __nv_bfloat16* __restrict__ W,
    const float* __restrict__ bias, const float* __restrict__ bias2,
    float* __restrict__ Cout, int M, int O)
{
    constexpr int AST = 40;   // bf16 row stride (32 + 8 pad)
    __shared__ __nv_bfloat16 As[3][128 * AST];
    __shared__ __nv_bfloat16 Bs[3][64 * AST];

    const int tid  = threadIdx.x;
    const int warp = tid >> 5;
    const int lane = tid & 31;
    const int warpM = warp >> 1;      // 0..3
    const int warpN = warp & 1;       // 0..1
    const int row0 = blockIdx.y * 128;
    const int col0 = blockIdx.x * 64;

    const uint32_t sAs = (uint32_t)__cvta_generic_to_shared(&As[0][0]);
    const uint32_t sBs = (uint32_t)__cvta_generic_to_shared(&Bs[0][0]);
    constexpr uint32_t AS_STAGE = 128 * AST * 2;
    constexpr uint32_t BS_STAGE = 64 * AST * 2;

    auto load_stage = [&](int kt, int s) {
        const int k0 = kt * 32;
#pragma unroll
        for (int p = 0; p < 2; p++) {
            int idx = tid + p * 256;
            int r = idx >> 2, c = idx & 3;
            int gm = row0 + r;
            const __nv_bfloat16* src = A + (size_t)(gm < M ? gm : M - 1) * KP + k0 + c * 8;
            uint32_t dst = sAs + s * AS_STAGE + (uint32_t)(r * AST + c * 8) * 2;
            cp16(dst, src, (gm < M) ? 16 : 0);
        }
        {
            int r = tid >> 2, c = tid & 3;
            int go = col0 + r;
            const __nv_bfloat16* src = W + (size_t)(go < O ? go : O - 1) * KP + k0 + c * 8;
            uint32_t dst = sBs + s * BS_STAGE + (uint32_t)(r * AST + c * 8) * 2;
            cp16(dst, src, (go < O) ? 16 : 0);
        }
    };

    float acc[2][4][4] = {};

    load_stage(0, 0); cp_commit();
    load_stage(1, 1); cp_commit();

    constexpr int NKT = KP / 32;   // 24
    for (int kt = 0; kt < NKT; kt++) {
        const int s = kt % 3;
        if (kt + 2 < NKT) load_stage(kt + 2, (kt + 2) % 3);
        cp_commit();
        cp_wait2();
        __syncthreads();

        const uint32_t aBase = sAs + s * AS_STAGE;
        const uint32_t bBase = sBs + s * BS_STAGE;
#pragma unroll
        for (int h = 0; h < 2; h++) {
            uint32_t afr[2][4], bfr[2][4];
#pragma unroll
            for (int mt = 0; mt < 2; mt++) {
                uint32_t addr = aBase +
                    (uint32_t)((warpM * 32 + mt * 16 + (lane & 15)) * AST +
                               h * 16 + (lane >> 4) * 8) * 2;
                ldsm4(afr[mt], addr);
            }
#pragma unroll
            for (int nt2 = 0; nt2 < 2; nt2++) {
                uint32_t addr = bBase +
                    (uint32_t)((warpN * 32 + nt2 * 16 + (lane & 15)) * AST +
                               h * 16 + (lane >> 4) * 8) * 2;
                ldsm4(bfr[nt2], addr);
            }
#pragma unroll
            for (int mt = 0; mt < 2; mt++)
#pragma unroll
                for (int nt = 0; nt < 4; nt++) {
                    uint32_t b0 = (nt & 1) ? bfr[nt >> 1][1] : bfr[nt >> 1][0];
                    uint32_t b1 = (nt & 1) ? bfr[nt >> 1][3] : bfr[nt >> 1][2];
                    mma16816(acc[mt][nt], afr[mt], b0, b1);
                }
        }
        __syncthreads();
    }

#pragma unroll
    for (int mt = 0; mt < 2; mt++) {
#pragma unroll
        for (int nt = 0; nt < 4; nt++) {
#pragma unroll
            for (int e = 0; e < 4; e++) {
                int m = row0 + warpM * 32 + mt * 16 + (lane >> 2) + (e >= 2 ? 8 : 0);
                int o = col0 + warpN * 32 + nt * 8 + 2 * (lane & 3) + (e & 1);
                if (m >= M || o >= O) continue;
                if (MODE == 1) {
                    float v = acc[mt][nt][e] + bias[o];
                    int b = m / Sc, ss = m % Sc;
                    int hh = o >> 5, d = o & 31;
                    g_valh[(((size_t)(b * Hc + hh)) * Sc + ss) * 32 + d] = __float2half(v);
                } else if (MODE == 2) {
                    if (o < OFFC) g_off[(size_t)m * OFFC + o] = acc[mt][nt][e] + bias[o];
                    else          g_logit[(size_t)m * ATTC + (o - OFFC)] = acc[mt][nt][e] + bias2[o - OFFC];
                } else {
                    Cout[(size_t)m * O + o] = acc[mt][nt][e] + bias[o];
                }
            }
        }
    }
}

// ---------------------------------------------------------------------------
// Fused sampler — fp16 gathers, writes decomposed (hi|lo|hi) bf16 A-operand.
// ---------------------------------------------------------------------------
__global__ __launch_bounds__(256) void sample_kernel(
    const float* __restrict__ priors,
    const int* __restrict__ map_shapes,
    const int* __restrict__ start_ids)
{
    const int m = blockIdx.x;
    const int b = (m >= Nn) ? 1 : 0;

    __shared__ int2  s_tab[ATTC][8];
    __shared__ float s_logit[ATTC];
    __shared__ float s_wh[Lc][2];
    __shared__ int   s_start[Lc];

    const int tid = threadIdx.x;
    if (tid < Lc) {
        s_wh[tid][0] = (float)map_shapes[tid * 2 + 1];  // W
        s_wh[tid][1] = (float)map_shapes[tid * 2 + 0];  // H
        s_start[tid] = start_ids[tid];
    }
    for (int i = tid; i < ATTC; i += 256) s_logit[i] = g_logit[(size_t)m * ATTC + i];
    __syncthreads();

    if (tid < ATTC) {
        const int h  = tid / NPT;
        const int lp = tid % NPT;
        const int l  = lp / Pc;
        const float ox = g_off[(size_t)m * OFFC + tid * 3 + 0];
        const float oy = g_off[(size_t)m * OFFC + tid * 3 + 1];
        const float oz = g_off[(size_t)m * OFFC + tid * 3 + 2];
        const float Wl = s_wh[l][0], Hl = s_wh[l][1];
        const float px = priors[((size_t)m * Lc + l) * 2 + 0];
        const float py = priors[((size_t)m * Lc + l) * 2 + 1];
        const float lx = px + ox / Wl;
        const float ly = py + oy / Hl;
        const float lz = (float)l * (1.0f / (Lc - 1)) + oz;

        float mx = -1e30f;
        for (int j = 0; j < NPT; j++) mx = fmaxf(mx, s_logit[h * NPT + j]);
        float sum = 0.f;
        for (int j = 0; j < NPT; j++) sum += __expf(s_logit[h * NPT + j] - mx);
        const float a = __expf(s_logit[tid] - mx) / sum;

        float z = fminf(fmaxf(lz, 0.f), 1.f) * (float)(Lc - 1);
        int z0 = min((int)z, Lc - 2);
        float wz = z - (float)z0;

#pragma unroll
        for (int q = 0; q < 2; q++) {
            const int lvl = z0 + q;
            const float wl = a * (q ? wz : (1.f - wz));
            const float Wf = s_wh[lvl][0], Hf = s_wh[lvl][1];
            const int Wi = (int)Wf, Hi = (int)Hf;
            const int offb = s_start[lvl];
            const float x = lx * Wf - 0.5f;
            const float y = ly * Hf - 0.5f;
            const float x0f = floorf(x), y0f = floorf(y);
            const float dx = x - x0f, dy = y - y0f;
            const int x0 = (int)x0f, y0 = (int)y0f;

            const float cw[4] = {(1.f - dx) * (1.f - dy), dx * (1.f - dy),
                                 (1.f - dx) * dy,          dx * dy};
            const int cx[4] = {x0, x0 + 1, x0, x0 + 1};
            const int cy[4] = {y0, y0, y0 + 1, y0 + 1};
#pragma unroll
            for (int c = 0; c < 4; c++) {
                const bool valid = (cx[c] >= 0) & (cx[c] < Wi) & (cy[c] >= 0) & (cy[c] < Hi);
                const int idx = valid ? (offb + cy[c] * Wi + cx[c]) : 0;
                const float w = valid ? (wl * cw[c]) : 0.f;
                s_tab[tid][q * 4 + c] = make_int2(idx, __float_as_int(w));
            }
        }
    }
    __syncthreads();

    const int warp = tid >> 5;
    const int lane = tid & 31;
    const int sub  = lane >> 3;
    const int ch   = lane & 7;

    const uint2* __restrict__ vb =
        (const uint2*)g_valh + (size_t)(b * Hc + warp) * Sc * 8;  // 8 x 8B per pixel

    float4 acc = make_float4(0.f, 0.f, 0.f, 0.f);
#pragma unroll
    for (int g = 0; g < 5; g++) {
        const int t = warp * NPT + g * 4 + sub;
#pragma unroll
        for (int c = 0; c < 8; c++) {
            const int2 e = s_tab[t][c];
            const float w = __int_as_float(e.y);
            if (w != 0.f) {
                const uint2 raw = __ldg(&vb[e.x * 8 + ch]);
                const float2 f01 = __half22float2(*(const __half2*)&raw.x);
                const float2 f23 = __half22float2(*(const __half2*)&raw.y);
                acc.x += w * f01.x;
                acc.y += w * f01.y;
                acc.z += w * f23.x;
                acc.w += w * f23.y;
            }
        }
    }
#pragma unroll
    for (int d = 8; d < 32; d <<= 1) {
        acc.x += __shfl_xor_sync(0xFFFFFFFFu, acc.x, d);
        acc.y += __shfl_xor_sync(0xFFFFFFFFu, acc.y, d);
        acc.z += __shfl_xor_sync(0xFFFFFFFFu, acc.z, d);
        acc.w += __shfl_xor_sync(0xFFFFFFFFu, acc.w, d);
    }
    if (lane < 8) {
        float v[4] = {acc.x, acc.y, acc.z, acc.w};
        size_t base = (size_t)m * KP + warp * 32 + ch * 4;
#pragma unroll
        for (int j = 0; j < 4; j++) {
            __nv_bfloat16 hi = __float2bfloat16(v[j]);
            __nv_bfloat16 lo = __float2bfloat16(v[j] - __bfloat162float(hi));
            gA_w[base + j]       = hi;
            gA_w[base + 256 + j] = lo;
            gA_w[base + 512 + j] = hi;
        }
    }
}

// ---------------------------------------------------------------------------
// kernel_launch
// ---------------------------------------------------------------------------
extern "C" void kernel_launch(void* const* d_in, const int* in_sizes, int n_in,
                              void* d_out, int out_size)
{
    const float* in_feats  = (const float*)d_in[0];
    const float* priors    = (const float*)d_in[1];
    const float* sfeats    = (const float*)d_in[2];
    const float* W_off     = (const float*)d_in[3];
    const float* b_off     = (const float*)d_in[4];
    const float* W_attn    = (const float*)d_in[5];
    const float* b_attn    = (const float*)d_in[6];
    const float* W_val     = (const float*)d_in[7];
    const float* b_val     = (const float*)d_in[8];
    const float* W_out     = (const float*)d_in[9];
    const float* b_out     = (const float*)d_in[10];
    const int*   shapes    = (const int*)d_in[11];
    const int*   start_ids = (const int*)d_in[12];

    __nv_bfloat16 *pA_in, *pA_sf, *pA_w, *pW_oa, *pW_val, *pW_out;
    cudaGetSymbolAddress((void**)&pA_in,  gA_in);
    cudaGetSymbolAddress((void**)&pA_sf,  gA_sf);
    cudaGetSymbolAddress((void**)&pA_w,   gA_w);
    cudaGetSymbolAddress((void**)&pW_oa,  gW_oa);
    cudaGetSymbolAddress((void**)&pW_val, gW_val);
    cudaGetSymbolAddress((void**)&pW_out, gW_out);

    decomp_a<<<(Mtot * 256 + 255) / 256, 256>>>(in_feats, pA_in, Mtot * 256);
    decomp_a<<<(Mtot * 256 + 255) / 256, 256>>>(sfeats,  pA_sf, Mtot * 256);
    decomp_w_all<<<1152, 256>>>(W_off, W_attn, W_val, W_out);

    const int gridM = (Mtot + 127) / 128;   // 86

    // Value projection -> g_valh (fp16)
    gemm_bf16<1><<<dim3(4, gridM), 256>>>(pA_sf, pW_val, b_val, nullptr, nullptr, Mtot, 256);
    // Merged offset+attn projection -> g_off / g_logit
    gemm_bf16<2><<<dim3(10, gridM), 256>>>(pA_in, pW_oa, b_off, b_attn, nullptr, Mtot, OAC);
    // Fused sampler -> gA_w (decomposed)
    sample_kernel<<<Mtot, 256>>>(priors, shapes, start_ids);
    // Output projection -> d_out
    gemm_bf16<4><<<dim3(4, gridM), 256>>>(pA_w, pW_out, b_out, nullptr, (float*)d_out, Mtot, 256);
}

// round 7
// speedup vs baseline: 3.5075x; 1.4491x over previous
#include <cuda_runtime.h>
#include <cuda_fp16.h>
#include <math.h>
#include <stdint.h>

// Problem constants
constexpr int Bc   = 2;
constexpr int Nn   = 5456;
constexpr int Sc   = 5456;
constexpr int Hc   = 8;
constexpr int Lc   = 5;
constexpr int Pc   = 4;
constexpr int Kin  = 256;
constexpr int Mtot = Bc * Nn;          // 10912
constexpr int NPT  = Lc * Pc;          // 20
constexpr int OFFC = Hc * NPT * 3;     // 480
constexpr int ATTC = Hc * NPT;         // 160
constexpr int OPRJ = 256 + OFFC + ATTC; // 896: [val | off | attn]

// Scratch (static device globals — allocation-free)
__device__ __half g_valh[(size_t)Bc * Hc * Sc * 32];   // [B,H,S,32] fp16
__device__ float g_off[(size_t)Mtot * OFFC];
__device__ float g_logit[(size_t)Mtot * ATTC];
__device__ __half gA_in[(size_t)Mtot * Kin];           // fp16 in_feats
__device__ __half gA_sf[(size_t)Mtot * Kin];           // fp16 sample_feats
__device__ __half gA_w [(size_t)Mtot * Kin];           // fp16 weighted
__device__ __half gW_all[OPRJ * Kin];                  // [val|off|attn] rows
__device__ __half gW_out[256 * Kin];

// ---------------------------------------------------------------------------
// PTX helpers
// ---------------------------------------------------------------------------
__device__ __forceinline__ void cp16(uint32_t dst, const void* src, int sz) {
    asm volatile("cp.async.cg.shared.global [%0], [%1], 16, %2;\n"
                 :: "r"(dst), "l"(src), "r"(sz));
}
__device__ __forceinline__ void cp_commit() {
    asm volatile("cp.async.commit_group;\n");
}
__device__ __forceinline__ void cp_wait2() {
    asm volatile("cp.async.wait_group 2;\n");
}
__device__ __forceinline__ void ldsm4(uint32_t* r, uint32_t a) {
    asm volatile("ldmatrix.sync.aligned.m8n8.x4.shared.b16 {%0,%1,%2,%3}, [%4];\n"
                 : "=r"(r[0]), "=r"(r[1]), "=r"(r[2]), "=r"(r[3]) : "r"(a));
}
__device__ __forceinline__ void mma16816(float* c, const uint32_t* a,
                                         uint32_t b0, uint32_t b1) {
    asm volatile(
        "mma.sync.aligned.m16n8k16.row.col.f32.f16.f16.f32 "
        "{%0,%1,%2,%3},{%4,%5,%6,%7},{%8,%9},{%0,%1,%2,%3};\n"
        : "+f"(c[0]), "+f"(c[1]), "+f"(c[2]), "+f"(c[3])
        : "r"(a[0]), "r"(a[1]), "r"(a[2]), "r"(a[3]), "r"(b0), "r"(b1));
}

// ---------------------------------------------------------------------------
// Convert both activation matrices fp32 -> fp16 (one fused launch)
// ---------------------------------------------------------------------------
__global__ __launch_bounds__(256) void conv_a(
    const float* __restrict__ in, const float* __restrict__ sf)
{
    int i = blockIdx.x * 256 + threadIdx.x;   // grid covers Mtot*256
    gA_in[i] = __float2half(in[i]);
    gA_sf[i] = __float2half(sf[i]);
}

// ---------------------------------------------------------------------------
// Convert all weights fp32 -> fp16: gW_all = [Wval | Woff | Wattn], gW_out
// ---------------------------------------------------------------------------
__global__ __launch_bounds__(256) void conv_w(
    const float* __restrict__ Wval, const float* __restrict__ Woff,
    const float* __restrict__ Wattn, const float* __restrict__ Wout)
{
    int i = blockIdx.x * 256 + threadIdx.x;   // 1152 * 256 total
    int row = i >> 8, k = i & 255;
    if (row < 256)       gW_all[i] = __float2half(Wval[(size_t)row * Kin + k]);
    else if (row < 736)  gW_all[i] = __float2half(Woff[(size_t)(row - 256) * Kin + k]);
    else if (row < OPRJ) gW_all[i] = __float2half(Wattn[(size_t)(row - 736) * Kin + k]);
    else gW_out[(size_t)(row - OPRJ) * Kin + k] = __float2half(Wout[(size_t)(row - OPRJ) * Kin + k]);
}

// ---------------------------------------------------------------------------
// fp16 tensor-core GEMM: C[m,o] = sum_k A[m,k] * W[o,k] (+bias per range)
// BM=128, BN=64, BK=32, K=256 (8 k-tiles), 3-stage cp.async, 256 threads.
// MODE 0 (projection, O=896): A per CTA = (col<256 ? A0=sf : A1=in);
//   o<256 -> g_valh fp16 (+bias_val), o<736 -> g_off (+bias_off),
//   else -> g_logit (+bias_attn)
// MODE 1 (output, O=256): A = A0 (gA_w), Cout fp32 (+bias_val)
// ---------------------------------------------------------------------------
template <int MODE>
__global__ __launch_bounds__(256) void gemm_f16(
    const __half* __restrict__ A0, const __half* __restrict__ A1,
    const __half* __restrict__ W,
    const float* __restrict__ bias_val, const float* __restrict__ bias_off,
    const float* __restrict__ bias_attn,
    float* __restrict__ Cout, int M, int O)
{
    constexpr int AST = 40;   // half row stride (32 + 8 pad)
    __shared__ __half As[3][128 * AST];
    __shared__ __half Bs[3][64 * AST];

    const int tid  = threadIdx.x;
    const int warp = tid >> 5;
    const int lane = tid & 31;
    const int warpM = warp >> 1;      // 0..3
    const int warpN = warp & 1;       // 0..1
    const int row0 = blockIdx.y * 128;
    const int col0 = blockIdx.x * 64;

    const __half* __restrict__ A = (MODE == 0 && col0 >= 256) ? A1 : A0;

    const uint32_t sAs = (uint32_t)__cvta_generic_to_shared(&As[0][0]);
    const uint32_t sBs = (uint32_t)__cvta_generic_to_shared(&Bs[0][0]);
    constexpr uint32_t AS_STAGE = 128 * AST * 2;
    constexpr uint32_t BS_STAGE = 64 * AST * 2;

    auto load_stage = [&](int kt, int s) {
        const int k0 = kt * 32;
#pragma unroll
        for (int p = 0; p < 2; p++) {
            int idx = tid + p * 256;
            int r = idx >> 2, c = idx & 3;
            int gm = row0 + r;
            const __half* src = A + (size_t)(gm < M ? gm : M - 1) * Kin + k0 + c * 8;
            uint32_t dst = sAs + s * AS_STAGE + (uint32_t)(r * AST + c * 8) * 2;
            cp16(dst, src, (gm < M) ? 16 : 0);
        }
        {
            int r = tid >> 2, c = tid & 3;
            int go = col0 + r;
            const __half* src = W + (size_t)(go < O ? go : O - 1) * Kin + k0 + c * 8;
            uint32_t dst = sBs + s * BS_STAGE + (uint32_t)(r * AST + c * 8) * 2;
            cp16(dst, src, (go < O) ? 16 : 0);
        }
    };

    float acc[2][4][4] = {};

    load_stage(0, 0); cp_commit();
    load_stage(1, 1); cp_commit();

    constexpr int NKT = Kin / 32;   // 8
    for (int kt = 0; kt < NKT; kt++) {
        const int s = kt % 3;
        if (kt + 2 < NKT) load_stage(kt + 2, (kt + 2) % 3);
        cp_commit();
        cp_wait2();
        __syncthreads();

        const uint32_t aBase = sAs + s * AS_STAGE;
        const uint32_t bBase = sBs + s * BS_STAGE;
#pragma unroll
        for (int h = 0; h < 2; h++) {
            uint32_t afr[2][4], bfr[2][4];
#pragma unroll
            for (int mt = 0; mt < 2; mt++) {
                uint32_t addr = aBase +
                    (uint32_t)((warpM * 32 + mt * 16 + (lane & 15)) * AST +
                               h * 16 + (lane >> 4) * 8) * 2;
                ldsm4(afr[mt], addr);
            }
#pragma unroll
            for (int nt2 = 0; nt2 < 2; nt2++) {
                uint32_t addr = bBase +
                    (uint32_t)((warpN * 32 + nt2 * 16 + (lane & 15)) * AST +
                               h * 16 + (lane >> 4) * 8) * 2;
                ldsm4(bfr[nt2], addr);
            }
#pragma unroll
            for (int mt = 0; mt < 2; mt++)
#pragma unroll
                for (int nt = 0; nt < 4; nt++) {
                    uint32_t b0 = (nt & 1) ? bfr[nt >> 1][1] : bfr[nt >> 1][0];
                    uint32_t b1 = (nt & 1) ? bfr[nt >> 1][3] : bfr[nt >> 1][2];
                    mma16816(acc[mt][nt], afr[mt], b0, b1);
                }
        }
        __syncthreads();
    }

#pragma unroll
    for (int mt = 0; mt < 2; mt++) {
#pragma unroll
        for (int nt = 0; nt < 4; nt++) {
#pragma unroll
            for (int e = 0; e < 4; e++) {
                int m = row0 + warpM * 32 + mt * 16 + (lane >> 2) + (e >= 2 ? 8 : 0);
                int o = col0 + warpN * 32 + nt * 8 + 2 * (lane & 3) + (e & 1);
                if (m >= M || o >= O) continue;
                float v = acc[mt][nt][e];
                if (MODE == 0) {
                    if (o < 256) {
                        int b = m / Sc, ss = m % Sc;
                        int hh = o >> 5, d = o & 31;
                        g_valh[(((size_t)(b * Hc + hh)) * Sc + ss) * 32 + d] =
                            __float2half(v + bias_val[o]);
                    } else if (o < 736) {
                        g_off[(size_t)m * OFFC + (o - 256)] = v + bias_off[o - 256];
                    } else {
                        g_logit[(size_t)m * ATTC + (o - 736)] = v + bias_attn[o - 736];
                    }
                } else {
                    Cout[(size_t)m * O + o] = v + bias_val[o];
                }
            }
        }
    }
}

// ---------------------------------------------------------------------------
// Fused sampler — fp16 gathers, writes fp16 weighted (gA_w) directly.
// ---------------------------------------------------------------------------
__global__ __launch_bounds__(256) void sample_kernel(
    const float* __restrict__ priors,
    const int* __restrict__ map_shapes,
    const int* __restrict__ start_ids)
{
    const int m = blockIdx.x;
    const int b = (m >= Nn) ? 1 : 0;

    __shared__ int2  s_tab[ATTC][8];
    __shared__ float s_logit[ATTC];
    __shared__ float s_wh[Lc][2];
    __shared__ int   s_start[Lc];

    const int tid = threadIdx.x;
    if (tid < Lc) {
        s_wh[tid][0] = (float)map_shapes[tid * 2 + 1];  // W
        s_wh[tid][1] = (float)map_shapes[tid * 2 + 0];  // H
        s_start[tid] = start_ids[tid];
    }
    for (int i = tid; i < ATTC; i += 256) s_logit[i] = g_logit[(size_t)m * ATTC + i];
    __syncthreads();

    if (tid < ATTC) {
        const int h  = tid / NPT;
        const int lp = tid % NPT;
        const int l  = lp / Pc;
        const float ox = g_off[(size_t)m * OFFC + tid * 3 + 0];
        const float oy = g_off[(size_t)m * OFFC + tid * 3 + 1];
        const float oz = g_off[(size_t)m * OFFC + tid * 3 + 2];
        const float Wl = s_wh[l][0], Hl = s_wh[l][1];
        const float px = priors[((size_t)m * Lc + l) * 2 + 0];
        const float py = priors[((size_t)m * Lc + l) * 2 + 1];
        const float lx = px + ox / Wl;
        const float ly = py + oy / Hl;
        const float lz = (float)l * (1.0f / (Lc - 1)) + oz;

        float mx = -1e30f;
        for (int j = 0; j < NPT; j++) mx = fmaxf(mx, s_logit[h * NPT + j]);
        float sum = 0.f;
        for (int j = 0; j < NPT; j++) sum += __expf(s_logit[h * NPT + j] - mx);
        const float a = __expf(s_logit[tid] - mx) / sum;

        float z = fminf(fmaxf(lz, 0.f), 1.f) * (float)(Lc - 1);
        int z0 = min((int)z, Lc - 2);
        float wz = z - (float)z0;

#pragma unroll
        for (int q = 0; q < 2; q++) {
            const int lvl = z0 + q;
            const float wl = a * (q ? wz : (1.f - wz));
            const float Wf = s_wh[lvl][0], Hf = s_wh[lvl][1];
            const int Wi = (int)Wf, Hi = (int)Hf;
            const int offb = s_start[lvl];
            const float x = lx * Wf - 0.5f;
            const float y = ly * Hf - 0.5f;
            const float x0f = floorf(x), y0f = floorf(y);
            const float dx = x - x0f, dy = y - y0f;
            const int x0 = (int)x0f, y0 = (int)y0f;

            const float cw[4] = {(1.f - dx) * (1.f - dy), dx * (1.f - dy),
                                 (1.f - dx) * dy,          dx * dy};
            const int cx[4] = {x0, x0 + 1, x0, x0 + 1};
            const int cy[4] = {y0, y0, y0 + 1, y0 + 1};
#pragma unroll
            for (int c = 0; c < 4; c++) {
                const bool valid = (cx[c] >= 0) & (cx[c] < Wi) & (cy[c] >= 0) & (cy[c] < Hi);
                const int idx = valid ? (offb + cy[c] * Wi + cx[c]) : 0;
                const float w = valid ? (wl * cw[c]) : 0.f;
                s_tab[tid][q * 4 + c] = make_int2(idx, __float_as_int(w));
            }
        }
    }
    __syncthreads();

    const int warp = tid >> 5;
    const int lane = tid & 31;
    const int sub  = lane >> 3;
    const int ch   = lane & 7;

    const uint2* __restrict__ vb =
        (const uint2*)g_valh + (size_t)(b * Hc + warp) * Sc * 8;  // 8 x 8B per pixel

    float4 acc = make_float4(0.f, 0.f, 0.f, 0.f);
#pragma unroll
    for (int g = 0; g < 5; g++) {
        const int t = warp * NPT + g * 4 + sub;
#pragma unroll
        for (int c = 0; c < 8; c++) {
            const int2 e = s_tab[t][c];
            const float w = __int_as_float(e.y);
            if (w != 0.f) {
                const uint2 raw = __ldg(&vb[e.x * 8 + ch]);
                const float2 f01 = __half22float2(*(const __half2*)&raw.x);
                const float2 f23 = __half22float2(*(const __half2*)&raw.y);
                acc.x += w * f01.x;
                acc.y += w * f01.y;
                acc.z += w * f23.x;
                acc.w += w * f23.y;
            }
        }
    }
#pragma unroll
    for (int d = 8; d < 32; d <<= 1) {
        acc.x += __shfl_xor_sync(0xFFFFFFFFu, acc.x, d);
        acc.y += __shfl_xor_sync(0xFFFFFFFFu, acc.y, d);
        acc.z += __shfl_xor_sync(0xFFFFFFFFu, acc.z, d);
        acc.w += __shfl_xor_sync(0xFFFFFFFFu, acc.w, d);
    }
    if (lane < 8) {
        __half2 h01 = __floats2half2_rn(acc.x, acc.y);
        __half2 h23 = __floats2half2_rn(acc.z, acc.w);
        uint2 pack;
        pack.x = *(uint32_t*)&h01;
        pack.y = *(uint32_t*)&h23;
        ((uint2*)gA_w)[((size_t)m * 256 + warp * 32 + ch * 4) >> 2] = pack;
    }
}

// ---------------------------------------------------------------------------
// kernel_launch
// ---------------------------------------------------------------------------
extern "C" void kernel_launch(void* const* d_in, const int* in_sizes, int n_in,
                              void* d_out, int out_size)
{
    const float* in_feats  = (const float*)d_in[0];
    const float* priors    = (const float*)d_in[1];
    const float* sfeats    = (const float*)d_in[2];
    const float* W_off     = (const float*)d_in[3];
    const float* b_off     = (const float*)d_in[4];
    const float* W_attn    = (const float*)d_in[5];
    const float* b_attn    = (const float*)d_in[6];
    const float* W_val     = (const float*)d_in[7];
    const float* b_val     = (const float*)d_in[8];
    const float* W_out     = (const float*)d_in[9];
    const float* b_out     = (const float*)d_in[10];
    const int*   shapes    = (const int*)d_in[11];
    const int*   start_ids = (const int*)d_in[12];

    __half *pA_in, *pA_sf, *pA_w, *pW_all, *pW_out;
    cudaGetSymbolAddress((void**)&pA_in,  gA_in);
    cudaGetSymbolAddress((void**)&pA_sf,  gA_sf);
    cudaGetSymbolAddress((void**)&pA_w,   gA_w);
    cudaGetSymbolAddress((void**)&pW_all, gW_all);
    cudaGetSymbolAddress((void**)&pW_out, gW_out);

    // fp32 -> fp16 conversions
    conv_a<<<Mtot, 256>>>(in_feats, sfeats);
    conv_w<<<1152, 256>>>(W_val, W_off, W_attn, W_out);

    const int gridM = (Mtot + 127) / 128;   // 86

    // Combined projection GEMM: [val | off | attn], O=896
    gemm_f16<0><<<dim3(OPRJ / 64, gridM), 256>>>(
        pA_sf, pA_in, pW_all, b_val, b_off, b_attn, nullptr, Mtot, OPRJ);
    // Fused sampler -> gA_w (fp16)
    sample_kernel<<<Mtot, 256>>>(priors, shapes, start_ids);
    // Output projection -> d_out (fp32)
    gemm_f16<1><<<dim3(4, gridM), 256>>>(
        pA_w, nullptr, pW_out, b_out, nullptr, nullptr, (float*)d_out, Mtot, 256);
}

// round 8
// speedup vs baseline: 3.8828x; 1.1070x over previous
#include <cuda_runtime.h>
#include <cuda_fp16.h>
#include <math.h>
#include <stdint.h>

// Problem constants
constexpr int Bc   = 2;
constexpr int Nn   = 5456;
constexpr int Sc   = 5456;
constexpr int Hc   = 8;
constexpr int Lc   = 5;
constexpr int Pc   = 4;
constexpr int Kin  = 256;
constexpr int Mtot = Bc * Nn;          // 10912
constexpr int NPT  = Lc * Pc;          // 20
constexpr int OFFC = Hc * NPT * 3;     // 480
constexpr int ATTC = Hc * NPT;         // 160
constexpr int OPRJ = 256 + OFFC + ATTC; // 896: [val | off | attn]

// Scratch (static device globals — allocation-free)
__device__ __half g_valh[(size_t)Bc * Hc * Sc * 32];   // [B,H,S,32] fp16
__device__ float g_off[(size_t)Mtot * OFFC];
__device__ float g_logit[(size_t)Mtot * ATTC];
__device__ __half gA_in[(size_t)Mtot * Kin];           // fp16 in_feats
__device__ __half gA_sf[(size_t)Mtot * Kin];           // fp16 sample_feats
__device__ __half gA_w [(size_t)Mtot * Kin];           // fp16 weighted
__device__ __half gW_all[OPRJ * Kin];                  // [val|off|attn] rows
__device__ __half gW_out[256 * Kin];

// ---------------------------------------------------------------------------
// PTX helpers
// ---------------------------------------------------------------------------
__device__ __forceinline__ void cp16(uint32_t dst, const void* src, int sz) {
    asm volatile("cp.async.cg.shared.global [%0], [%1], 16, %2;\n"
                 :: "r"(dst), "l"(src), "r"(sz));
}
__device__ __forceinline__ void cp_commit() {
    asm volatile("cp.async.commit_group;\n");
}
__device__ __forceinline__ void cp_wait2() {
    asm volatile("cp.async.wait_group 2;\n");
}
__device__ __forceinline__ void ldsm4(uint32_t* r, uint32_t a) {
    asm volatile("ldmatrix.sync.aligned.m8n8.x4.shared.b16 {%0,%1,%2,%3}, [%4];\n"
                 : "=r"(r[0]), "=r"(r[1]), "=r"(r[2]), "=r"(r[3]) : "r"(a));
}
__device__ __forceinline__ void mma16816(float* c, const uint32_t* a,
                                         uint32_t b0, uint32_t b1) {
    asm volatile(
        "mma.sync.aligned.m16n8k16.row.col.f32.f16.f16.f32 "
        "{%0,%1,%2,%3},{%4,%5,%6,%7},{%8,%9},{%0,%1,%2,%3};\n"
        : "+f"(c[0]), "+f"(c[1]), "+f"(c[2]), "+f"(c[3])
        : "r"(a[0]), "r"(a[1]), "r"(a[2]), "r"(a[3]), "r"(b0), "r"(b1));
}

// ---------------------------------------------------------------------------
// Convert both activation matrices fp32 -> fp16 (vectorized, one launch)
// Each thread handles one float4 (4 elems) from each source.
// ---------------------------------------------------------------------------
__global__ __launch_bounds__(256) void conv_a(
    const float4* __restrict__ in, const float4* __restrict__ sf)
{
    int i = blockIdx.x * 256 + threadIdx.x;   // grid covers Mtot*64 float4s
    {
        float4 a = in[i];
        __half2 h0 = __floats2half2_rn(a.x, a.y);
        __half2 h1 = __floats2half2_rn(a.z, a.w);
        uint2 p;
        p.x = *(uint32_t*)&h0; p.y = *(uint32_t*)&h1;
        ((uint2*)gA_in)[i] = p;
    }
    {
        float4 a = sf[i];
        __half2 h0 = __floats2half2_rn(a.x, a.y);
        __half2 h1 = __floats2half2_rn(a.z, a.w);
        uint2 p;
        p.x = *(uint32_t*)&h0; p.y = *(uint32_t*)&h1;
        ((uint2*)gA_sf)[i] = p;
    }
}

// ---------------------------------------------------------------------------
// Convert all weights fp32 -> fp16: gW_all = [Wval | Woff | Wattn], gW_out
// ---------------------------------------------------------------------------
__global__ __launch_bounds__(256) void conv_w(
    const float* __restrict__ Wval, const float* __restrict__ Woff,
    const float* __restrict__ Wattn, const float* __restrict__ Wout)
{
    int i = blockIdx.x * 256 + threadIdx.x;   // 1152 * 256 total
    int row = i >> 8, k = i & 255;
    if (row < 256)       gW_all[i] = __float2half(Wval[(size_t)row * Kin + k]);
    else if (row < 736)  gW_all[i] = __float2half(Woff[(size_t)(row - 256) * Kin + k]);
    else if (row < OPRJ) gW_all[i] = __float2half(Wattn[(size_t)(row - 736) * Kin + k]);
    else gW_out[(size_t)(row - OPRJ) * Kin + k] = __float2half(Wout[(size_t)(row - OPRJ) * Kin + k]);
}

// ---------------------------------------------------------------------------
// fp16 tensor-core GEMM: C[m,o] = sum_k A[m,k] * W[o,k] (+bias per range)
// BM=128, BN=64, BK=32, K=256 (8 k-tiles), 3-stage cp.async, 256 threads.
// MODE 0 (projection, O=896): A per CTA = (col<256 ? A0=sf : A1=in);
//   o<256 -> g_valh fp16 (+bias_val), o<736 -> g_off (+bias_off),
//   else -> g_logit (+bias_attn)
// MODE 1 (output, O=256): A = A0 (gA_w), Cout fp32 (+bias_val)
// ---------------------------------------------------------------------------
template <int MODE>
__global__ __launch_bounds__(256) void gemm_f16(
    const __half* __restrict__ A0, const __half* __restrict__ A1,
    const __half* __restrict__ W,
    const float* __restrict__ bias_val, const float* __restrict__ bias_off,
    const float* __restrict__ bias_attn,
    float* __restrict__ Cout, int M, int O)
{
    constexpr int AST = 40;   // half row stride (32 + 8 pad)
    __shared__ __half As[3][128 * AST];
    __shared__ __half Bs[3][64 * AST];

    const int tid  = threadIdx.x;
    const int warp = tid >> 5;
    const int lane = tid & 31;
    const int warpM = warp >> 1;      // 0..3
    const int warpN = warp & 1;       // 0..1
    const int row0 = blockIdx.y * 128;
    const int col0 = blockIdx.x * 64;

    const __half* __restrict__ A = (MODE == 0 && col0 >= 256) ? A1 : A0;

    const uint32_t sAs = (uint32_t)__cvta_generic_to_shared(&As[0][0]);
    const uint32_t sBs = (uint32_t)__cvta_generic_to_shared(&Bs[0][0]);
    constexpr uint32_t AS_STAGE = 128 * AST * 2;
    constexpr uint32_t BS_STAGE = 64 * AST * 2;

    auto load_stage = [&](int kt, int s) {
        const int k0 = kt * 32;
#pragma unroll
        for (int p = 0; p < 2; p++) {
            int idx = tid + p * 256;
            int r = idx >> 2, c = idx & 3;
            int gm = row0 + r;
            const __half* src = A + (size_t)(gm < M ? gm : M - 1) * Kin + k0 + c * 8;
            uint32_t dst = sAs + s * AS_STAGE + (uint32_t)(r * AST + c * 8) * 2;
            cp16(dst, src, (gm < M) ? 16 : 0);
        }
        {
            int r = tid >> 2, c = tid & 3;
            int go = col0 + r;
            const __half* src = W + (size_t)(go < O ? go : O - 1) * Kin + k0 + c * 8;
            uint32_t dst = sBs + s * BS_STAGE + (uint32_t)(r * AST + c * 8) * 2;
            cp16(dst, src, (go < O) ? 16 : 0);
        }
    };

    float acc[2][4][4] = {};

    load_stage(0, 0); cp_commit();
    load_stage(1, 1); cp_commit();

    constexpr int NKT = Kin / 32;   // 8
    for (int kt = 0; kt < NKT; kt++) {
        const int s = kt % 3;
        if (kt + 2 < NKT) load_stage(kt + 2, (kt + 2) % 3);
        cp_commit();
        cp_wait2();
        __syncthreads();

        const uint32_t aBase = sAs + s * AS_STAGE;
        const uint32_t bBase = sBs + s * BS_STAGE;
#pragma unroll
        for (int h = 0; h < 2; h++) {
            uint32_t afr[2][4], bfr[2][4];
#pragma unroll
            for (int mt = 0; mt < 2; mt++) {
                uint32_t addr = aBase +
                    (uint32_t)((warpM * 32 + mt * 16 + (lane & 15)) * AST +
                               h * 16 + (lane >> 4) * 8) * 2;
                ldsm4(afr[mt], addr);
            }
#pragma unroll
            for (int nt2 = 0; nt2 < 2; nt2++) {
                uint32_t addr = bBase +
                    (uint32_t)((warpN * 32 + nt2 * 16 + (lane & 15)) * AST +
                               h * 16 + (lane >> 4) * 8) * 2;
                ldsm4(bfr[nt2], addr);
            }
#pragma unroll
            for (int mt = 0; mt < 2; mt++)
#pragma unroll
                for (int nt = 0; nt < 4; nt++) {
                    uint32_t b0 = (nt & 1) ? bfr[nt >> 1][1] : bfr[nt >> 1][0];
                    uint32_t b1 = (nt & 1) ? bfr[nt >> 1][3] : bfr[nt >> 1][2];
                    mma16816(acc[mt][nt], afr[mt], b0, b1);
                }
        }
        __syncthreads();
    }

#pragma unroll
    for (int mt = 0; mt < 2; mt++) {
#pragma unroll
        for (int nt = 0; nt < 4; nt++) {
#pragma unroll
            for (int e = 0; e < 4; e++) {
                int m = row0 + warpM * 32 + mt * 16 + (lane >> 2) + (e >= 2 ? 8 : 0);
                int o = col0 + warpN * 32 + nt * 8 + 2 * (lane & 3) + (e & 1);
                if (m >= M || o >= O) continue;
                float v = acc[mt][nt][e];
                if (MODE == 0) {
                    if (o < 256) {
                        int b = m / Sc, ss = m % Sc;
                        int hh = o >> 5, d = o & 31;
                        g_valh[(((size_t)(b * Hc + hh)) * Sc + ss) * 32 + d] =
                            __float2half(v + bias_val[o]);
                    } else if (o < 736) {
                        g_off[(size_t)m * OFFC + (o - 256)] = v + bias_off[o - 256];
                    } else {
                        g_logit[(size_t)m * ATTC + (o - 736)] = v + bias_attn[o - 736];
                    }
                } else {
                    Cout[(size_t)m * O + o] = v + bias_val[o];
                }
            }
        }
    }
}

// ---------------------------------------------------------------------------
// Fused sampler.
// Phase 1 (160 threads, one per point): loc + softmax -> 8 corner entries
//   {byte_offset = idx*64, weight} per point in smem.
// Phase 2: warp = head; lane = corner(lane>>2) * 4 + ch(lane&3).
//   8 corners in parallel, each lane loads 16B (8 fp16 channels) per point.
//   20 iterations of LDS.64 + IADD + LDG.128 + 8 cvt + 8 FFMA.
//   Corner-reduce via shfl_xor(4,8,16); lanes 0..3 write 16B fp16 each.
// ---------------------------------------------------------------------------
__global__ __launch_bounds__(256) void sample_kernel(
    const float* __restrict__ priors,
    const int* __restrict__ map_shapes,
    const int* __restrict__ start_ids)
{
    const int m = blockIdx.x;
    const int b = (m >= Nn) ? 1 : 0;

    __shared__ int2  s_tab[ATTC][8];
    __shared__ float s_logit[ATTC];
    __shared__ float s_wh[Lc][2];
    __shared__ int   s_start[Lc];

    const int tid = threadIdx.x;
    if (tid < Lc) {
        s_wh[tid][0] = (float)map_shapes[tid * 2 + 1];  // W
        s_wh[tid][1] = (float)map_shapes[tid * 2 + 0];  // H
        s_start[tid] = start_ids[tid];
    }
    for (int i = tid; i < ATTC; i += 256) s_logit[i] = g_logit[(size_t)m * ATTC + i];
    __syncthreads();

    if (tid < ATTC) {
        const int h  = tid / NPT;
        const int lp = tid % NPT;
        const int l  = lp / Pc;
        const float ox = g_off[(size_t)m * OFFC + tid * 3 + 0];
        const float oy = g_off[(size_t)m * OFFC + tid * 3 + 1];
        const float oz = g_off[(size_t)m * OFFC + tid * 3 + 2];
        const float Wl = s_wh[l][0], Hl = s_wh[l][1];
        const float px = priors[((size_t)m * Lc + l) * 2 + 0];
        const float py = priors[((size_t)m * Lc + l) * 2 + 1];
        const float lx = px + ox / Wl;
        const float ly = py + oy / Hl;
        const float lz = (float)l * (1.0f / (Lc - 1)) + oz;

        float mx = -1e30f;
        for (int j = 0; j < NPT; j++) mx = fmaxf(mx, s_logit[h * NPT + j]);
        float sum = 0.f;
        for (int j = 0; j < NPT; j++) sum += __expf(s_logit[h * NPT + j] - mx);
        const float a = __expf(s_logit[tid] - mx) / sum;

        float z = fminf(fmaxf(lz, 0.f), 1.f) * (float)(Lc - 1);
        int z0 = min((int)z, Lc - 2);
        float wz = z - (float)z0;

#pragma unroll
        for (int q = 0; q < 2; q++) {
            const int lvl = z0 + q;
            const float wl = a * (q ? wz : (1.f - wz));
            const float Wf = s_wh[lvl][0], Hf = s_wh[lvl][1];
            const int Wi = (int)Wf, Hi = (int)Hf;
            const int offb = s_start[lvl];
            const float x = lx * Wf - 0.5f;
            const float y = ly * Hf - 0.5f;
            const float x0f = floorf(x), y0f = floorf(y);
            const float dx = x - x0f, dy = y - y0f;
            const int x0 = (int)x0f, y0 = (int)y0f;

            const float cw[4] = {(1.f - dx) * (1.f - dy), dx * (1.f - dy),
                                 (1.f - dx) * dy,          dx * dy};
            const int cx[4] = {x0, x0 + 1, x0, x0 + 1};
            const int cy[4] = {y0, y0, y0 + 1, y0 + 1};
#pragma unroll
            for (int c = 0; c < 4; c++) {
                const bool valid = (cx[c] >= 0) & (cx[c] < Wi) & (cy[c] >= 0) & (cy[c] < Hi);
                const int idx = valid ? (offb + cy[c] * Wi + cx[c]) : 0;
                const float w = valid ? (wl * cw[c]) : 0.f;
                s_tab[tid][q * 4 + c] = make_int2(idx << 6, __float_as_int(w));
            }
        }
    }
    __syncthreads();

    const int warp = tid >> 5;              // head
    const int lane = tid & 31;
    const int sub  = lane >> 2;             // corner 0..7
    const int ch   = lane & 3;              // 16B channel group

    const char* __restrict__ vbase =
        (const char*)g_valh + (size_t)(b * Hc + warp) * Sc * 64 + ch * 16;

    float acc[8] = {};
#pragma unroll
    for (int p = 0; p < NPT; p++) {
        const int2 e = s_tab[warp * NPT + p][sub];
        const float w = __int_as_float(e.y);
        if (w != 0.f) {
            const uint4 raw = __ldg((const uint4*)(vbase + e.x));
            float2 f;
            f = __half22float2(*(const __half2*)&raw.x);
            acc[0] += w * f.x; acc[1] += w * f.y;
            f = __half22float2(*(const __half2*)&raw.y);
            acc[2] += w * f.x; acc[3] += w * f.y;
            f = __half22float2(*(const __half2*)&raw.z);
            acc[4] += w * f.x; acc[5] += w * f.y;
            f = __half22float2(*(const __half2*)&raw.w);
            acc[6] += w * f.x; acc[7] += w * f.y;
        }
    }
    // reduce over the 8 corner sub-groups (lane bits 2,3,4)
#pragma unroll
    for (int d = 4; d < 32; d <<= 1) {
#pragma unroll
        for (int j = 0; j < 8; j++)
            acc[j] += __shfl_xor_sync(0xFFFFFFFFu, acc[j], d);
    }
    if (lane < 4) {
        __half2 h0 = __floats2half2_rn(acc[0], acc[1]);
        __half2 h1 = __floats2half2_rn(acc[2], acc[3]);
        __half2 h2 = __floats2half2_rn(acc[4], acc[5]);
        __half2 h3 = __floats2half2_rn(acc[6], acc[7]);
        uint4 pack;
        pack.x = *(uint32_t*)&h0;
        pack.y = *(uint32_t*)&h1;
        pack.z = *(uint32_t*)&h2;
        pack.w = *(uint32_t*)&h3;
        ((uint4*)gA_w)[(size_t)m * 32 + warp * 4 + ch] = pack;
    }
}

// ---------------------------------------------------------------------------
// kernel_launch
// ---------------------------------------------------------------------------
extern "C" void kernel_launch(void* const* d_in, const int* in_sizes, int n_in,
                              void* d_out, int out_size)
{
    const float* in_feats  = (const float*)d_in[0];
    const float* priors    = (const float*)d_in[1];
    const float* sfeats    = (const float*)d_in[2];
    const float* W_off     = (const float*)d_in[3];
    const float* b_off     = (const float*)d_in[4];
    const float* W_attn    = (const float*)d_in[5];
    const float* b_attn    = (const float*)d_in[6];
    const float* W_val     = (const float*)d_in[7];
    const float* b_val     = (const float*)d_in[8];
    const float* W_out     = (const float*)d_in[9];
    const float* b_out     = (const float*)d_in[10];
    const int*   shapes    = (const int*)d_in[11];
    const int*   start_ids = (const int*)d_in[12];

    __half *pA_in, *pA_sf, *pA_w, *pW_all, *pW_out;
    cudaGetSymbolAddress((void**)&pA_in,  gA_in);
    cudaGetSymbolAddress((void**)&pA_sf,  gA_sf);
    cudaGetSymbolAddress((void**)&pA_w,   gA_w);
    cudaGetSymbolAddress((void**)&pW_all, gW_all);
    cudaGetSymbolAddress((void**)&pW_out, gW_out);

    // fp32 -> fp16 conversions
    conv_a<<<Mtot / 4, 256>>>((const float4*)in_feats, (const float4*)sfeats);
    conv_w<<<1152, 256>>>(W_val, W_off, W_attn, W_out);

    const int gridM = (Mtot + 127) / 128;   // 86

    // Combined projection GEMM: [val | off | attn], O=896
    gemm_f16<0><<<dim3(OPRJ / 64, gridM), 256>>>(
        pA_sf, pA_in, pW_all, b_val, b_off, b_attn, nullptr, Mtot, OPRJ);
    // Fused sampler -> gA_w (fp16)
    sample_kernel<<<Mtot, 256>>>(priors, shapes, start_ids);
    // Output projection -> d_out (fp32)
    gemm_f16<1><<<dim3(4, gridM), 256>>>(
        pA_w, nullptr, pW_out, b_out, nullptr, nullptr, (float*)d_out, Mtot, 256);
}